// round 16
// baseline (speedup 1.0000x reference)
#include <cuda_runtime.h>
#include <cuda_bf16.h>
#include <cuda_fp16.h>
#include <cuda_fp8.h>
#include <cstdint>

#define BB   2
#define CC   128
#define HH   48
#define NTOK 2304
#define NHEADS 8
#define CHH  16
#define KTOP 1843

typedef unsigned long long ull;

// ---------------- scratch ----------------
__device__ __nv_bfloat16 g_q16[BB*CC*NTOK];          // raw q bf16, [b*C+c][n]
__device__ __nv_bfloat16 g_kT[BB*NHEADS*NTOK*CHH];   // NORMALIZED K, [bh][n][ch-pair-permuted]
__device__ unsigned char g_v8[BB*CC*NTOK];           // v e4m3 (scaled), token-pair-permuted
__device__ float g_vsinv[BB*CC];                     // per-channel V inverse scale
__device__ __nv_bfloat16 g_aT[BB*NTOK*CC];           // attention out bf16, [b][n][c]
__device__ __nv_bfloat16 g_wo16[CC*CC];              // wo pre-converted bf16

// ---------------- fp8 helpers ----------------
__device__ __forceinline__ unsigned short pack2_e4m3(float lo, float hi) {
    unsigned short r;
    asm("cvt.rn.satfinite.e4m3x2.f32 %0, %1, %2;" : "=h"(r) : "f"(hi), "f"(lo));
    return r;
}
__device__ __forceinline__ unsigned f2e4m3(float f) {
    return (unsigned)__nv_cvt_float_to_fp8(f, __NV_SATFINITE, __NV_E4M3);
}
// monotone byte keymap over 4 packed e4m3 (forward)
__device__ __forceinline__ unsigned keymap4(unsigned u) {
    unsigned m = u & 0x80808080u;
    unsigned X = 0x80808080u | ((m >> 7) * 0x7Fu);
    return u ^ X;
}
// pair-permute slot map: u32 j (0..7) -> slot (pairs (j, j+4) adjacent)
__device__ __forceinline__ int sperm(int j) { return (j < 4) ? 2*j : 2*j - 7; }

// ---------------- mma wrappers ----------------
__device__ __forceinline__ void mma_bf16(float& c0, float& c1, float& c2, float& c3,
                                         unsigned a0, unsigned a1, unsigned a2, unsigned a3,
                                         unsigned b0, unsigned b1) {
    asm volatile("mma.sync.aligned.m16n8k16.row.col.f32.bf16.bf16.f32 "
                 "{%0,%1,%2,%3}, {%4,%5,%6,%7}, {%8,%9}, {%0,%1,%2,%3};"
                 : "+f"(c0), "+f"(c1), "+f"(c2), "+f"(c3)
                 : "r"(a0), "r"(a1), "r"(a2), "r"(a3), "r"(b0), "r"(b1));
}
__device__ __forceinline__ void mma_e4m3(float& c0, float& c1, float& c2, float& c3,
                                         unsigned a0, unsigned a1, unsigned a2, unsigned a3,
                                         unsigned b0, unsigned b1) {
    asm volatile("mma.sync.aligned.m16n8k32.row.col.f32.e4m3.e4m3.f32 "
                 "{%0,%1,%2,%3}, {%4,%5,%6,%7}, {%8,%9}, {%0,%1,%2,%3};"
                 : "+f"(c0), "+f"(c1), "+f"(c2), "+f"(c3)
                 : "r"(a0), "r"(a1), "r"(a2), "r"(a3), "r"(b0), "r"(b1));
}

// =================================================================
// Kernel 1: FUSED qkv convs, ONE channel x all 3 types per block.
// 576 threads, 4 CONSECUTIVE px/thread (float4 loads), 2 CTAs/SM.
// grid = BB*CC = 256 blocks. Blocks 0..31 also convert wo -> bf16.
// Plane order: 0=q 1=k 2=v
// =================================================================
#define QKV_SPST (NTOK + 8)
#define QKV_SMEM_FLOATS (3*QKV_SPST + 3*32 + 3*9 + 2*18 + 2)
#define QKV_SMEM_BYTES  (QKV_SMEM_FLOATS * 4)

__global__ __launch_bounds__(576, 2) void qkv_kernel(
    const float* __restrict__ x,
    const float* __restrict__ wq, const float* __restrict__ wk, const float* __restrict__ wv,
    const float* __restrict__ dwq, const float* __restrict__ dwk, const float* __restrict__ dwv,
    const float* __restrict__ wo)
{
    extern __shared__ float smq[];
    float* sp   = smq;                       // [3][QKV_SPST]
    float* wpp  = smq + 3*QKV_SPST;          // [3][32]
    float* wdd  = wpp + 3*32;                // [3][9]
    float* redw = wdd + 3*9;                 // [2][18]
    float* s_sc = redw + 2*18;               // [2]: kinv, vsc

    const int b = blockIdx.x >> 7;
    const int c = blockIdx.x & 127;
    const int g = c >> 5;
    const int tid = threadIdx.x;
    const int lane = tid & 31;

    // side job: blocks 0..31 convert wo to bf16 (512 elems each)
    if (blockIdx.x < 32 && tid < 512)
        g_wo16[blockIdx.x*512 + tid] = __float2bfloat16(wo[blockIdx.x*512 + tid]);

    if (tid < 96) {
        int pl = tid >> 5, i = tid & 31;
        const float* w = (pl == 0) ? wq : (pl == 1) ? wk : wv;
        wpp[pl*32 + i] = w[c*32 + i];
    }
    if (tid < 27) {
        int pl = tid / 9, ki = tid % 9;
        const float* dw = (pl == 0) ? dwq : (pl == 1) ? dwk : dwv;
        wdd[pl*9 + ki] = dw[c*9 + ki];
    }
    __syncthreads();

    // pointwise grouped conv: float4 pixel quads, 3 planes share x loads
    const float4* xb4 = (const float4*)(x + (size_t)(b*CC + g*32) * NTOK) + tid;
    float a[3][4];
#pragma unroll
    for (int pl = 0; pl < 3; ++pl)
#pragma unroll
        for (int p = 0; p < 4; ++p) a[pl][p] = 0.f;
    for (int i = 0; i < 32; ++i) {
        const float w0 = wpp[0*32 + i], w1 = wpp[1*32 + i], w2 = wpp[2*32 + i];
        float4 xv = xb4[(size_t)i * (NTOK/4)];
        a[0][0] += w0*xv.x; a[0][1] += w0*xv.y; a[0][2] += w0*xv.z; a[0][3] += w0*xv.w;
        a[1][0] += w1*xv.x; a[1][1] += w1*xv.y; a[1][2] += w1*xv.z; a[1][3] += w1*xv.w;
        a[2][0] += w2*xv.x; a[2][1] += w2*xv.y; a[2][2] += w2*xv.z; a[2][3] += w2*xv.w;
    }
#pragma unroll
    for (int pl = 0; pl < 3; ++pl)
        ((float4*)(sp + pl*QKV_SPST))[tid] = make_float4(a[pl][0], a[pl][1], a[pl][2], a[pl][3]);
    __syncthreads();

    // depthwise 3x3 SAME on 3 planes + stats (k sumsq, v absmax)
    float d[3][4];
    float rv0 = 0.f, rv1 = 0.f;
#pragma unroll
    for (int j = 0; j < 4; ++j) {
        int n = tid*4 + j;
        int r = n / HH;
        int col = n - r*HH;
        float s0 = 0.f, s1 = 0.f, s2 = 0.f;
#pragma unroll
        for (int dy = 0; dy < 3; ++dy) {
            int rr = r + dy - 1;
            if ((unsigned)rr < (unsigned)HH) {
#pragma unroll
                for (int dx = 0; dx < 3; ++dx) {
                    int cc2 = col + dx - 1;
                    if ((unsigned)cc2 < (unsigned)HH) {
                        int nn = rr*HH + cc2;
                        int ki = dy*3 + dx;
                        s0 += wdd[0*9 + ki] * sp[0*QKV_SPST + nn];
                        s1 += wdd[1*9 + ki] * sp[1*QKV_SPST + nn];
                        s2 += wdd[2*9 + ki] * sp[2*QKV_SPST + nn];
                    }
                }
            }
        }
        d[0][j] = s0; d[1][j] = s1; d[2][j] = s2;
        rv0 += s1 * s1;
        rv1 = fmaxf(rv1, fabsf(s2));
    }

    // reductions across 18 warps
#pragma unroll
    for (int off = 16; off; off >>= 1) {
        rv0 += __shfl_xor_sync(0xffffffffu, rv0, off);
        rv1 = fmaxf(rv1, __shfl_xor_sync(0xffffffffu, rv1, off));
    }
    if (lane == 0) {
        int wi = tid >> 5;
        redw[wi]      = rv0;
        redw[18 + wi] = rv1;
    }
    __syncthreads();
    if (tid < 32) {
        float v0 = (tid < 18) ? redw[tid] : 0.f;
        float v1 = (tid < 18) ? redw[18 + tid] : 0.f;
#pragma unroll
        for (int off = 16; off; off >>= 1) {
            v0 += __shfl_xor_sync(0xffffffffu, v0, off);
            v1 = fmaxf(v1, __shfl_xor_sync(0xffffffffu, v1, off));
        }
        if (tid == 0) {
            s_sc[0] = 1.f / fmaxf(sqrtf(v0), 1e-12f);
            s_sc[1] = (v1 > 0.f) ? 240.f / v1 : 0.f;
            g_vsinv[b*CC + c] = (v1 > 0.f) ? v1 / 240.f : 0.f;
        }
    }
    __syncthreads();
    const float ksc = s_sc[0];
    const float vsc = s_sc[1];

    // epilogues (pixel quad is contiguous)
    {   // q raw bf16: 4 values = 8 bytes, one store
        unsigned u0 = ((unsigned)__bfloat16_as_ushort(__float2bfloat16(d[0][0])))
                    | ((unsigned)__bfloat16_as_ushort(__float2bfloat16(d[0][1])) << 16);
        unsigned u1 = ((unsigned)__bfloat16_as_ushort(__float2bfloat16(d[0][2])))
                    | ((unsigned)__bfloat16_as_ushort(__float2bfloat16(d[0][3])) << 16);
        *(uint2*)(g_q16 + (size_t)(b*CC + c)*NTOK + tid*4) = make_uint2(u0, u1);
    }
    {   // k normalized, pair-permuted channel slot (stride-16 scalar stores)
        const int bh = b*NHEADS + (c >> 4);
        const int ch = c & 15;
        const int pos = sperm(ch >> 1) * 2 + (ch & 1);
        __nv_bfloat16* kTp = g_kT + (size_t)bh*NTOK*CHH + pos;
#pragma unroll
        for (int j = 0; j < 4; ++j)
            kTp[(size_t)(tid*4 + j)*16] = __float2bfloat16(d[1][j] * ksc);
    }
    {   // v fp8, token-pair-permuted: quad -> one u32 store
        unsigned pv = (f2e4m3(d[2][0] * vsc))
                    | (f2e4m3(d[2][1] * vsc) << 8)
                    | (f2e4m3(d[2][2] * vsc) << 16)
                    | (f2e4m3(d[2][3] * vsc) << 24);
        int np = ((tid*4) & ~31) | (sperm(tid & 7) * 4);
        *(unsigned*)(g_v8 + (size_t)(b*CC + c)*NTOK + np) = pv;
    }
}

// =================================================================
// Kernel 2: fused attention (113.3us winner; P5 writes bf16 [b][n][c])
// grid = (144, 16), 512 threads, 2 CTA/SM
// =================================================================
#define SROWB 2320
#define ATTN_SM_S   (16*SROWB)
#define ATTN_SM_QA  512
#define ATTN_SM_SCR (16*256*4)
#define ATTN_SM_ZS  (16*16*4)
#define ATTN_SMEM_BYTES (ATTN_SM_S + ATTN_SM_QA + ATTN_SM_SCR + ATTN_SM_ZS)

__global__ __launch_bounds__(512, 2) void attn_kernel(const float* __restrict__ temperature)
{
    extern __shared__ unsigned char smraw[];
    unsigned char* smS = smraw;
    __nv_bfloat16* qA  = (__nv_bfloat16*)(smraw + ATTN_SM_S);
    float* scratch     = (float*)(smraw + ATTN_SM_S + ATTN_SM_QA);
    float* zs          = (float*)(smraw + ATTN_SM_S + ATTN_SM_QA + ATTN_SM_SCR);

    const int rt = blockIdx.x, bh = blockIdx.y;
    const int b = bh >> 3, h = bh & 7;
    const int bc0 = b*CC + h*CHH;
    const int row0 = rt * 16;
    const int tid = threadIdx.x;
    const int w = tid >> 5, lane = tid & 31;
    const float ts = temperature[h];

    // ---- phase 0: Q rows, L2-normalize over C_h, fold temperature ----
    if (tid < 256) {
        int r = tid >> 4, c = tid & 15;
        float qv = __bfloat162float(g_q16[(size_t)(bc0 + c)*NTOK + row0 + r]);
        float ss = qv * qv;
#pragma unroll
        for (int off = 8; off; off >>= 1) ss += __shfl_xor_sync(0xffffffffu, ss, off, 16);
        float qt = qv * ts / fmaxf(sqrtf(ss), 1e-12f);
        qA[r*16 + c] = __float2bfloat16(qt);
    }
    __syncthreads();

    // ---- phase 1: scores via bf16 mma -> keymapped e4m3 smem ----
    {
        const unsigned* qAu = (const unsigned*)qA;
        int r = lane >> 2, kx = (lane & 3) * 2;
        unsigned a0 = qAu[(r*16 + kx) >> 1];
        unsigned a1 = qAu[((r+8)*16 + kx) >> 1];
        unsigned a2 = qAu[(r*16 + kx + 8) >> 1];
        unsigned a3 = qAu[((r+8)*16 + kx + 8) >> 1];

        const ull* kT64 = (const ull*)(g_kT + (size_t)bh * NTOK * CHH);
        const int jl = lane >> 2, ko = lane & 3;
        const int cst = (lane & 3) * 2;
#pragma unroll
        for (int mb = 0; mb < 3; ++mb) {
            ull rbb[6];
#pragma unroll
            for (int m = 0; m < 6; ++m) {
                int j0 = w*144 + (mb*6 + m)*8;
                rbb[m] = kT64[(size_t)(j0 + jl)*4 + ko];
            }
#pragma unroll
            for (int m = 0; m < 6; ++m) {
                int j0 = w*144 + (mb*6 + m)*8;
                float c0 = 0.f, c1 = 0.f, c2 = 0.f, c3 = 0.f;
                mma_bf16(c0, c1, c2, c3, a0, a1, a2, a3,
                         (unsigned)rbb[m], (unsigned)(rbb[m] >> 32));
                int off = j0 + cst;
                unsigned comb = (unsigned)pack2_e4m3(c0, c1)
                              | ((unsigned)pack2_e4m3(c2, c3) << 16);
                comb = keymap4(comb);
                *(unsigned short*)(smS + r*SROWB + off)     = (unsigned short)comb;
                *(unsigned short*)(smS + (r+8)*SROWB + off) = (unsigned short)(comb >> 16);
            }
        }
    }
    __syncthreads();

    // ---- phase 2: half-row register cache + 4-pass binary search ----
    unsigned* srowU = (unsigned*)(smS + (size_t)w * SROWB);
    unsigned rr[9];
#pragma unroll
    for (int it = 0; it < 9; ++it) rr[it] = srowU[lane + it*32];

    int lo = 0, hi = 15;
#pragma unroll
    for (int pass = 0; pass < 4; ++pass) {
        int mid = (lo + hi + 1) >> 1;
        unsigned t4 = (unsigned)(mid << 4) * 0x01010101u;
        int cnt = 0;
#pragma unroll
        for (int it = 0; it < 9; ++it)
            cnt = __dp4a((int)__vsetgeu4(rr[it], t4), 0x01010101, cnt);
#pragma unroll
        for (int it = 9; it < 18; ++it)
            cnt = __dp4a((int)__vsetgeu4(srowU[lane + it*32], t4), 0x01010101, cnt);
#pragma unroll
        for (int off = 16; off; off >>= 1) cnt += __shfl_xor_sync(0xffffffffu, cnt, off);
        if (cnt >= KTOP) lo = mid; else hi = mid - 1;
    }
    const unsigned tk4 = ((unsigned)(lo << 4)) * 0x01010101u;

    // ---- phase 3: masked f16x2 softmax weights (shift by |ts|), in place ----
    {
        const float l2ef = 1.4426950408889634f;
        const float shift = fabsf(ts);
        const __half2 hl2e = __float2half2_rn(l2ef);
        const __half2 hb   = __float2half2_rn(-shift * l2ef);
#pragma unroll
        for (int it = 0; it < 18; ++it) {
            unsigned k = (it < 9) ? rr[it] : srowU[lane + it*32];
            unsigned mff = __vcmpgeu4(k, tk4);
            unsigned sb = (k & 0x80808080u) >> 7;
            unsigned u = (~k) ^ (sb * 0x7Fu);
            unsigned hlo, hhi;
            asm("cvt.rn.f16x2.e4m3x2 %0, %1;" : "=r"(hlo) : "h"((unsigned short)(u & 0xffffu)));
            asm("cvt.rn.f16x2.e4m3x2 %0, %1;" : "=r"(hhi) : "h"((unsigned short)(u >> 16)));
            __half2 alo = __hfma2(*(__half2*)&hlo, hl2e, hb);
            __half2 ahi = __hfma2(*(__half2*)&hhi, hl2e, hb);
            unsigned wlo, whi;
            asm("ex2.approx.f16x2 %0, %1;" : "=r"(wlo) : "r"(*(unsigned*)&alo));
            asm("ex2.approx.f16x2 %0, %1;" : "=r"(whi) : "r"(*(unsigned*)&ahi));
            unsigned short plo, phi;
            asm("cvt.rn.satfinite.e4m3x2.f16x2 %0, %1;" : "=h"(plo) : "r"(wlo));
            asm("cvt.rn.satfinite.e4m3x2.f16x2 %0, %1;" : "=h"(phi) : "r"(whi));
            srowU[lane + it*32] = ((unsigned)plo | ((unsigned)phi << 16)) & mff;
        }
    }
    __syncthreads();

    // ---- phase 4: PV via fp8 mma (LDG.64 V) + ones-column mma for Z ----
    float acc[8];
#pragma unroll
    for (int i = 0; i < 8; ++i) acc[i] = 0.f;
    float za0 = 0.f, za1 = 0.f, za2 = 0.f, za3 = 0.f;
    {
        const unsigned char* vb = g_v8 + (size_t)bc0 * NTOK;
        const int r = lane >> 2, ko = lane & 3, kx = ko * 4;
        const int nn = lane >> 2;
        const unsigned bz = (lane < 4) ? 0x38383838u : 0u;   // e4m3 1.0 in col 0
        for (int k0 = w*32; k0 < NTOK; k0 += 512) {
            unsigned A0 = *(const unsigned*)(smS + r*SROWB + k0 + kx);
            unsigned A1 = *(const unsigned*)(smS + (r+8)*SROWB + k0 + kx);
            unsigned A2 = *(const unsigned*)(smS + r*SROWB + k0 + kx + 16);
            unsigned A3 = *(const unsigned*)(smS + (r+8)*SROWB + k0 + kx + 16);
            ull bb01 = *(const ull*)(vb + (size_t)nn*NTOK + k0 + 8*ko);
            ull bb23 = *(const ull*)(vb + (size_t)(nn+8)*NTOK + k0 + 8*ko);
            mma_e4m3(acc[0], acc[1], acc[2], acc[3], A0, A1, A2, A3,
                     (unsigned)bb01, (unsigned)(bb01 >> 32));
            mma_e4m3(acc[4], acc[5], acc[6], acc[7], A0, A1, A2, A3,
                     (unsigned)bb23, (unsigned)(bb23 >> 32));
            mma_e4m3(za0, za1, za2, za3, A0, A1, A2, A3, bz, bz);
        }
    }
    {
        int r = lane >> 2, c2s = (lane & 3) * 2;
        float* sw = scratch + w*256;
        sw[r*16 + c2s]           = acc[0];
        sw[r*16 + c2s + 1]       = acc[1];
        sw[(r+8)*16 + c2s]       = acc[2];
        sw[(r+8)*16 + c2s + 1]   = acc[3];
        sw[r*16 + 8 + c2s]       = acc[4];
        sw[r*16 + 8 + c2s + 1]   = acc[5];
        sw[(r+8)*16 + 8 + c2s]   = acc[6];
        sw[(r+8)*16 + 8 + c2s+1] = acc[7];
        if ((lane & 3) == 0) {
            zs[w*16 + r]     = za0;
            zs[w*16 + 8 + r] = za2;
        }
    }
    __syncthreads();

    // ---- phase 5: cross-warp reduce, z-normalize, unscale, write bf16 [b][n][c] ----
    if (tid < 256) {
        int r = tid >> 4, c = tid & 15;
        float s = 0.f, zr = 0.f;
#pragma unroll
        for (int wi = 0; wi < 16; ++wi) {
            s  += scratch[wi*256 + r*16 + c];
            zr += zs[wi*16 + r];
        }
        float val = s / zr * g_vsinv[bc0 + c];
        g_aT[((size_t)b*NTOK + row0 + r)*CC + h*CHH + c] = __float2bfloat16(val);
    }
}

// =================================================================
// Kernel 3: out = x + wo @ attn via bf16 tensor cores.
// wo pre-converted (g_wo16), attn tile pre-converted [b][n][c] (g_aT).
// grid = (72, 2), 256 threads
// =================================================================
#define OC_STRIDE 136
#define OC_SMEM_BYTES ((128*OC_STRIDE + 32*OC_STRIDE) * 2)

__global__ __launch_bounds__(256) void outconv_kernel(
    const float* __restrict__ x, float* __restrict__ out)
{
    extern __shared__ __nv_bfloat16 smoc[];
    __nv_bfloat16* wos = smoc;                      // [128][136]
    __nv_bfloat16* ats = smoc + 128*OC_STRIDE;      // [32 tokens][136 channels]

    const int b  = blockIdx.y;
    const int n0 = blockIdx.x * 32;
    const int tid = threadIdx.x;

    {   // wo: 8192 u32 pairs, 32 per thread
        const unsigned* wsrc = (const unsigned*)g_wo16;
        for (int l = tid; l < 8192; l += 256) {
            int row = l >> 6, cp = l & 63;
            *(unsigned*)&wos[row*OC_STRIDE + cp*2] = wsrc[l];
        }
    }
    {   // attn tile: 2048 u32 pairs, 8 per thread
        const unsigned* asrc = (const unsigned*)(g_aT + (size_t)b*NTOK*CC) + (size_t)n0*64;
        for (int l = tid; l < 2048; l += 256) {
            int nl = l >> 6, cp = l & 63;
            *(unsigned*)&ats[nl*OC_STRIDE + cp*2] = asrc[l];
        }
    }
    __syncthreads();

    const int w = tid >> 5, lane = tid & 31;
    const int r = lane >> 2, kq = (lane & 3) * 2;

    float acc[4][4];
#pragma unroll
    for (int ng = 0; ng < 4; ++ng)
#pragma unroll
        for (int i = 0; i < 4; ++i) acc[ng][i] = 0.f;

#pragma unroll
    for (int kc = 0; kc < 8; ++kc) {
        const int k0 = kc * 16;
        unsigned a0 = *(const unsigned*)&wos[(w*16 + r)*OC_STRIDE + k0 + kq];
        unsigned a1 = *(const unsigned*)&wos[(w*16 + r + 8)*OC_STRIDE + k0 + kq];
        unsigned a2 = *(const unsigned*)&wos[(w*16 + r)*OC_STRIDE + k0 + kq + 8];
        unsigned a3 = *(const unsigned*)&wos[(w*16 + r + 8)*OC_STRIDE + k0 + kq + 8];
#pragma unroll
        for (int ng = 0; ng < 4; ++ng) {
            unsigned b0 = *(const unsigned*)&ats[(ng*8 + r)*OC_STRIDE + k0 + kq];
            unsigned b1 = *(const unsigned*)&ats[(ng*8 + r)*OC_STRIDE + k0 + kq + 8];
            mma_bf16(acc[ng][0], acc[ng][1], acc[ng][2], acc[ng][3],
                     a0, a1, a2, a3, b0, b1);
        }
    }

#pragma unroll
    for (int ng = 0; ng < 4; ++ng) {
        const int col = n0 + ng*8 + kq;
        size_t i0 = (size_t)(b*CC + w*16 + r)*NTOK + col;
        float2 x0 = *(const float2*)(x + i0);
        *(float2*)(out + i0) = make_float2(x0.x + acc[ng][0], x0.y + acc[ng][1]);
        size_t i1 = (size_t)(b*CC + w*16 + r + 8)*NTOK + col;
        float2 x1 = *(const float2*)(x + i1);
        *(float2*)(out + i1) = make_float2(x1.x + acc[ng][2], x1.y + acc[ng][3]);
    }
}

// =================================================================
extern "C" void kernel_launch(void* const* d_in, const int* in_sizes, int n_in,
                              void* d_out, int out_size)
{
    const float* x    = (const float*)d_in[0];
    const float* wq   = (const float*)d_in[1];
    const float* wk   = (const float*)d_in[2];
    const float* wv   = (const float*)d_in[3];
    const float* dwq  = (const float*)d_in[4];
    const float* dwk  = (const float*)d_in[5];
    const float* dwv  = (const float*)d_in[6];
    const float* wo   = (const float*)d_in[7];
    const float* temp = (const float*)d_in[8];
    float* out = (float*)d_out;

    cudaFuncSetAttribute(qkv_kernel, cudaFuncAttributeMaxDynamicSharedMemorySize, QKV_SMEM_BYTES);
    cudaFuncSetAttribute(attn_kernel, cudaFuncAttributeMaxDynamicSharedMemorySize, ATTN_SMEM_BYTES);
    cudaFuncSetAttribute(outconv_kernel, cudaFuncAttributeMaxDynamicSharedMemorySize, OC_SMEM_BYTES);

    qkv_kernel<<<BB*CC, 576, QKV_SMEM_BYTES>>>(x, wq, wk, wv, dwq, dwk, dwv, wo);
    attn_kernel<<<dim3(NTOK/16, BB*NHEADS), 512, ATTN_SMEM_BYTES>>>(temp);
    outconv_kernel<<<dim3(NTOK/32, BB), 256, OC_SMEM_BYTES>>>(x, out);
}

// round 17
// speedup vs baseline: 1.0700x; 1.0700x over previous
#include <cuda_runtime.h>
#include <cuda_bf16.h>
#include <cuda_fp16.h>
#include <cuda_fp8.h>
#include <cstdint>

#define BB   2
#define CC   128
#define HH   48
#define NTOK 2304
#define NHEADS 8
#define CHH  16
#define KTOP 1843

typedef unsigned long long ull;

// ---------------- scratch ----------------
__device__ __nv_bfloat16 g_q16[BB*CC*NTOK];          // raw q bf16, [b*C+c][n]
__device__ __nv_bfloat16 g_kT[BB*NHEADS*NTOK*CHH];   // NORMALIZED K, [bh][n][ch-pair-permuted]
__device__ unsigned char g_v8[BB*CC*NTOK];           // v e4m3 (scaled), token-pair-permuted
__device__ float g_vsinv[BB*CC];                     // per-channel V inverse scale
__device__ __nv_bfloat16 g_aT[BB*NTOK*CC];           // attention out bf16, [b][n][c]
__device__ __nv_bfloat16 g_wo16[CC*CC];              // wo pre-converted bf16

// ---------------- fp8 helpers ----------------
__device__ __forceinline__ unsigned short pack2_e4m3(float lo, float hi) {
    unsigned short r;
    asm("cvt.rn.satfinite.e4m3x2.f32 %0, %1, %2;" : "=h"(r) : "f"(hi), "f"(lo));
    return r;
}
__device__ __forceinline__ unsigned f2e4m3(float f) {
    return (unsigned)__nv_cvt_float_to_fp8(f, __NV_SATFINITE, __NV_E4M3);
}
// monotone byte keymap over 4 packed e4m3 (forward)
__device__ __forceinline__ unsigned keymap4(unsigned u) {
    unsigned m = u & 0x80808080u;
    unsigned X = 0x80808080u | ((m >> 7) * 0x7Fu);
    return u ^ X;
}
// pair-permute slot map: u32 j (0..7) -> slot (pairs (j, j+4) adjacent)
__device__ __forceinline__ int sperm(int j) { return (j < 4) ? 2*j : 2*j - 7; }

// ---------------- mma wrappers ----------------
__device__ __forceinline__ void mma_bf16(float& c0, float& c1, float& c2, float& c3,
                                         unsigned a0, unsigned a1, unsigned a2, unsigned a3,
                                         unsigned b0, unsigned b1) {
    asm volatile("mma.sync.aligned.m16n8k16.row.col.f32.bf16.bf16.f32 "
                 "{%0,%1,%2,%3}, {%4,%5,%6,%7}, {%8,%9}, {%0,%1,%2,%3};"
                 : "+f"(c0), "+f"(c1), "+f"(c2), "+f"(c3)
                 : "r"(a0), "r"(a1), "r"(a2), "r"(a3), "r"(b0), "r"(b1));
}
__device__ __forceinline__ void mma_e4m3(float& c0, float& c1, float& c2, float& c3,
                                         unsigned a0, unsigned a1, unsigned a2, unsigned a3,
                                         unsigned b0, unsigned b1) {
    asm volatile("mma.sync.aligned.m16n8k32.row.col.f32.e4m3.e4m3.f32 "
                 "{%0,%1,%2,%3}, {%4,%5,%6,%7}, {%8,%9}, {%0,%1,%2,%3};"
                 : "+f"(c0), "+f"(c1), "+f"(c2), "+f"(c3)
                 : "r"(a0), "r"(a1), "r"(a2), "r"(a3), "r"(b0), "r"(b1));
}

// =================================================================
// Kernel 1: FUSED qkv convs, ONE channel x all 3 types per block.
// 576 threads, 4 STRIDED px/thread (conflict-free smem), 2 CTAs/SM.
// grid = BB*CC = 256 blocks. Blocks 0..31 also convert wo -> bf16.
// Plane order: 0=q 1=k 2=v
// =================================================================
#define QKV_SPST (NTOK + 8)
#define QKV_SMEM_FLOATS (3*QKV_SPST + 3*32 + 3*9 + 2*18 + 2)
#define QKV_SMEM_BYTES  (QKV_SMEM_FLOATS * 4)

__global__ __launch_bounds__(576, 2) void qkv_kernel(
    const float* __restrict__ x,
    const float* __restrict__ wq, const float* __restrict__ wk, const float* __restrict__ wv,
    const float* __restrict__ dwq, const float* __restrict__ dwk, const float* __restrict__ dwv,
    const float* __restrict__ wo)
{
    extern __shared__ float smq[];
    float* sp   = smq;                       // [3][QKV_SPST]
    float* wpp  = smq + 3*QKV_SPST;          // [3][32]
    float* wdd  = wpp + 3*32;                // [3][9]
    float* redw = wdd + 3*9;                 // [2][18]
    float* s_sc = redw + 2*18;               // [2]: kinv, vsc

    const int b = blockIdx.x >> 7;
    const int c = blockIdx.x & 127;
    const int g = c >> 5;
    const int tid = threadIdx.x;
    const int lane = tid & 31;

    // side job: blocks 0..31 convert wo to bf16 (512 elems each)
    if (blockIdx.x < 32 && tid < 512)
        g_wo16[blockIdx.x*512 + tid] = __float2bfloat16(wo[blockIdx.x*512 + tid]);

    if (tid < 96) {
        int pl = tid >> 5, i = tid & 31;
        const float* w = (pl == 0) ? wq : (pl == 1) ? wk : wv;
        wpp[pl*32 + i] = w[c*32 + i];
    }
    if (tid < 27) {
        int pl = tid / 9, ki = tid % 9;
        const float* dw = (pl == 0) ? dwq : (pl == 1) ? dwk : dwv;
        wdd[pl*9 + ki] = dw[c*9 + ki];
    }
    __syncthreads();

    // pointwise grouped conv: 3 planes share x loads (strided pixels)
    const float* xb = x + (size_t)(b*CC + g*32) * NTOK + tid;
    float a[3][4];
#pragma unroll
    for (int pl = 0; pl < 3; ++pl)
#pragma unroll
        for (int p = 0; p < 4; ++p) a[pl][p] = 0.f;
    for (int i = 0; i < 32; ++i) {
        const float w0 = wpp[0*32 + i], w1 = wpp[1*32 + i], w2 = wpp[2*32 + i];
        const float* xi = xb + (size_t)i*NTOK;
#pragma unroll
        for (int p = 0; p < 4; ++p) {
            float xv = xi[p*576];
            a[0][p] += w0*xv; a[1][p] += w1*xv; a[2][p] += w2*xv;
        }
    }
#pragma unroll
    for (int pl = 0; pl < 3; ++pl)
#pragma unroll
        for (int p = 0; p < 4; ++p) sp[pl*QKV_SPST + tid + p*576] = a[pl][p];
    __syncthreads();

    // depthwise 3x3 SAME on 3 planes + stats (k sumsq, v absmax)
    float d[3][4];
    float rv0 = 0.f, rv1 = 0.f;
#pragma unroll
    for (int p = 0; p < 4; ++p) {
        int n = tid + p*576;
        int r = n / HH;
        int col = n - r*HH;
        float s0 = 0.f, s1 = 0.f, s2 = 0.f;
#pragma unroll
        for (int dy = 0; dy < 3; ++dy) {
            int rr = r + dy - 1;
            if ((unsigned)rr < (unsigned)HH) {
#pragma unroll
                for (int dx = 0; dx < 3; ++dx) {
                    int cc2 = col + dx - 1;
                    if ((unsigned)cc2 < (unsigned)HH) {
                        int nn = rr*HH + cc2;
                        int ki = dy*3 + dx;
                        s0 += wdd[0*9 + ki] * sp[0*QKV_SPST + nn];
                        s1 += wdd[1*9 + ki] * sp[1*QKV_SPST + nn];
                        s2 += wdd[2*9 + ki] * sp[2*QKV_SPST + nn];
                    }
                }
            }
        }
        d[0][p] = s0; d[1][p] = s1; d[2][p] = s2;
        rv0 += s1 * s1;
        rv1 = fmaxf(rv1, fabsf(s2));
    }

    // reductions across 18 warps
#pragma unroll
    for (int off = 16; off; off >>= 1) {
        rv0 += __shfl_xor_sync(0xffffffffu, rv0, off);
        rv1 = fmaxf(rv1, __shfl_xor_sync(0xffffffffu, rv1, off));
    }
    if (lane == 0) {
        int wi = tid >> 5;
        redw[wi]      = rv0;
        redw[18 + wi] = rv1;
    }
    __syncthreads();
    if (tid < 32) {
        float v0 = (tid < 18) ? redw[tid] : 0.f;
        float v1 = (tid < 18) ? redw[18 + tid] : 0.f;
#pragma unroll
        for (int off = 16; off; off >>= 1) {
            v0 += __shfl_xor_sync(0xffffffffu, v0, off);
            v1 = fmaxf(v1, __shfl_xor_sync(0xffffffffu, v1, off));
        }
        if (tid == 0) {
            s_sc[0] = 1.f / fmaxf(sqrtf(v0), 1e-12f);
            s_sc[1] = (v1 > 0.f) ? 240.f / v1 : 0.f;
            g_vsinv[b*CC + c] = (v1 > 0.f) ? v1 / 240.f : 0.f;
        }
    }
    __syncthreads();
    const float ksc = s_sc[0];
    const float vsc = s_sc[1];

    // epilogues
    {   // q raw bf16
        __nv_bfloat16* q0 = g_q16 + (size_t)(b*CC + c)*NTOK;
#pragma unroll
        for (int p = 0; p < 4; ++p)
            q0[tid + p*576] = __float2bfloat16(d[0][p]);
    }
    {   // k normalized, pair-permuted channel slot
        const int bh = b*NHEADS + (c >> 4);
        const int ch = c & 15;
        const int pos = sperm(ch >> 1) * 2 + (ch & 1);
        __nv_bfloat16* kTp = g_kT + (size_t)bh*NTOK*CHH + pos;
#pragma unroll
        for (int p = 0; p < 4; ++p) {
            int n = tid + p*576;
            kTp[(size_t)n*16] = __float2bfloat16(d[1][p] * ksc);
        }
    }
    {   // v fp8, token-pair-permuted within 32-byte blocks
        unsigned char* v0 = g_v8 + (size_t)(b*CC + c)*NTOK;
#pragma unroll
        for (int p = 0; p < 4; ++p) {
            int n = tid + p*576;
            int np = (n & ~31) | (sperm((n >> 2) & 7) * 4) | (n & 3);
            v0[np] = (unsigned char)f2e4m3(d[2][p] * vsc);
        }
    }
}

// =================================================================
// Kernel 2: fused attention (113.3us winner; P5 writes bf16 [b][n][c])
// grid = (144, 16), 512 threads, 2 CTA/SM
// =================================================================
#define SROWB 2320
#define ATTN_SM_S   (16*SROWB)
#define ATTN_SM_QA  512
#define ATTN_SM_SCR (16*256*4)
#define ATTN_SM_ZS  (16*16*4)
#define ATTN_SMEM_BYTES (ATTN_SM_S + ATTN_SM_QA + ATTN_SM_SCR + ATTN_SM_ZS)

__global__ __launch_bounds__(512, 2) void attn_kernel(const float* __restrict__ temperature)
{
    extern __shared__ unsigned char smraw[];
    unsigned char* smS = smraw;
    __nv_bfloat16* qA  = (__nv_bfloat16*)(smraw + ATTN_SM_S);
    float* scratch     = (float*)(smraw + ATTN_SM_S + ATTN_SM_QA);
    float* zs          = (float*)(smraw + ATTN_SM_S + ATTN_SM_QA + ATTN_SM_SCR);

    const int rt = blockIdx.x, bh = blockIdx.y;
    const int b = bh >> 3, h = bh & 7;
    const int bc0 = b*CC + h*CHH;
    const int row0 = rt * 16;
    const int tid = threadIdx.x;
    const int w = tid >> 5, lane = tid & 31;
    const float ts = temperature[h];

    // ---- phase 0: Q rows, L2-normalize over C_h, fold temperature ----
    if (tid < 256) {
        int r = tid >> 4, c = tid & 15;
        float qv = __bfloat162float(g_q16[(size_t)(bc0 + c)*NTOK + row0 + r]);
        float ss = qv * qv;
#pragma unroll
        for (int off = 8; off; off >>= 1) ss += __shfl_xor_sync(0xffffffffu, ss, off, 16);
        float qt = qv * ts / fmaxf(sqrtf(ss), 1e-12f);
        qA[r*16 + c] = __float2bfloat16(qt);
    }
    __syncthreads();

    // ---- phase 1: scores via bf16 mma -> keymapped e4m3 smem ----
    {
        const unsigned* qAu = (const unsigned*)qA;
        int r = lane >> 2, kx = (lane & 3) * 2;
        unsigned a0 = qAu[(r*16 + kx) >> 1];
        unsigned a1 = qAu[((r+8)*16 + kx) >> 1];
        unsigned a2 = qAu[(r*16 + kx + 8) >> 1];
        unsigned a3 = qAu[((r+8)*16 + kx + 8) >> 1];

        const ull* kT64 = (const ull*)(g_kT + (size_t)bh * NTOK * CHH);
        const int jl = lane >> 2, ko = lane & 3;
        const int cst = (lane & 3) * 2;
#pragma unroll
        for (int mb = 0; mb < 3; ++mb) {
            ull rbb[6];
#pragma unroll
            for (int m = 0; m < 6; ++m) {
                int j0 = w*144 + (mb*6 + m)*8;
                rbb[m] = kT64[(size_t)(j0 + jl)*4 + ko];
            }
#pragma unroll
            for (int m = 0; m < 6; ++m) {
                int j0 = w*144 + (mb*6 + m)*8;
                float c0 = 0.f, c1 = 0.f, c2 = 0.f, c3 = 0.f;
                mma_bf16(c0, c1, c2, c3, a0, a1, a2, a3,
                         (unsigned)rbb[m], (unsigned)(rbb[m] >> 32));
                int off = j0 + cst;
                unsigned comb = (unsigned)pack2_e4m3(c0, c1)
                              | ((unsigned)pack2_e4m3(c2, c3) << 16);
                comb = keymap4(comb);
                *(unsigned short*)(smS + r*SROWB + off)     = (unsigned short)comb;
                *(unsigned short*)(smS + (r+8)*SROWB + off) = (unsigned short)(comb >> 16);
            }
        }
    }
    __syncthreads();

    // ---- phase 2: half-row register cache + 4-pass binary search ----
    unsigned* srowU = (unsigned*)(smS + (size_t)w * SROWB);
    unsigned rr[9];
#pragma unroll
    for (int it = 0; it < 9; ++it) rr[it] = srowU[lane + it*32];

    int lo = 0, hi = 15;
#pragma unroll
    for (int pass = 0; pass < 4; ++pass) {
        int mid = (lo + hi + 1) >> 1;
        unsigned t4 = (unsigned)(mid << 4) * 0x01010101u;
        int cnt = 0;
#pragma unroll
        for (int it = 0; it < 9; ++it)
            cnt = __dp4a((int)__vsetgeu4(rr[it], t4), 0x01010101, cnt);
#pragma unroll
        for (int it = 9; it < 18; ++it)
            cnt = __dp4a((int)__vsetgeu4(srowU[lane + it*32], t4), 0x01010101, cnt);
#pragma unroll
        for (int off = 16; off; off >>= 1) cnt += __shfl_xor_sync(0xffffffffu, cnt, off);
        if (cnt >= KTOP) lo = mid; else hi = mid - 1;
    }
    const unsigned tk4 = ((unsigned)(lo << 4)) * 0x01010101u;

    // ---- phase 3: masked f16x2 softmax weights (shift by |ts|), in place ----
    {
        const float l2ef = 1.4426950408889634f;
        const float shift = fabsf(ts);
        const __half2 hl2e = __float2half2_rn(l2ef);
        const __half2 hb   = __float2half2_rn(-shift * l2ef);
#pragma unroll
        for (int it = 0; it < 18; ++it) {
            unsigned k = (it < 9) ? rr[it] : srowU[lane + it*32];
            unsigned mff = __vcmpgeu4(k, tk4);
            unsigned sb = (k & 0x80808080u) >> 7;
            unsigned u = (~k) ^ (sb * 0x7Fu);
            unsigned hlo, hhi;
            asm("cvt.rn.f16x2.e4m3x2 %0, %1;" : "=r"(hlo) : "h"((unsigned short)(u & 0xffffu)));
            asm("cvt.rn.f16x2.e4m3x2 %0, %1;" : "=r"(hhi) : "h"((unsigned short)(u >> 16)));
            __half2 alo = __hfma2(*(__half2*)&hlo, hl2e, hb);
            __half2 ahi = __hfma2(*(__half2*)&hhi, hl2e, hb);
            unsigned wlo, whi;
            asm("ex2.approx.f16x2 %0, %1;" : "=r"(wlo) : "r"(*(unsigned*)&alo));
            asm("ex2.approx.f16x2 %0, %1;" : "=r"(whi) : "r"(*(unsigned*)&ahi));
            unsigned short plo, phi;
            asm("cvt.rn.satfinite.e4m3x2.f16x2 %0, %1;" : "=h"(plo) : "r"(wlo));
            asm("cvt.rn.satfinite.e4m3x2.f16x2 %0, %1;" : "=h"(phi) : "r"(whi));
            srowU[lane + it*32] = ((unsigned)plo | ((unsigned)phi << 16)) & mff;
        }
    }
    __syncthreads();

    // ---- phase 4: PV via fp8 mma (LDG.64 V) + ones-column mma for Z ----
    float acc[8];
#pragma unroll
    for (int i = 0; i < 8; ++i) acc[i] = 0.f;
    float za0 = 0.f, za1 = 0.f, za2 = 0.f, za3 = 0.f;
    {
        const unsigned char* vb = g_v8 + (size_t)bc0 * NTOK;
        const int r = lane >> 2, ko = lane & 3, kx = ko * 4;
        const int nn = lane >> 2;
        const unsigned bz = (lane < 4) ? 0x38383838u : 0u;   // e4m3 1.0 in col 0
        for (int k0 = w*32; k0 < NTOK; k0 += 512) {
            unsigned A0 = *(const unsigned*)(smS + r*SROWB + k0 + kx);
            unsigned A1 = *(const unsigned*)(smS + (r+8)*SROWB + k0 + kx);
            unsigned A2 = *(const unsigned*)(smS + r*SROWB + k0 + kx + 16);
            unsigned A3 = *(const unsigned*)(smS + (r+8)*SROWB + k0 + kx + 16);
            ull bb01 = *(const ull*)(vb + (size_t)nn*NTOK + k0 + 8*ko);
            ull bb23 = *(const ull*)(vb + (size_t)(nn+8)*NTOK + k0 + 8*ko);
            mma_e4m3(acc[0], acc[1], acc[2], acc[3], A0, A1, A2, A3,
                     (unsigned)bb01, (unsigned)(bb01 >> 32));
            mma_e4m3(acc[4], acc[5], acc[6], acc[7], A0, A1, A2, A3,
                     (unsigned)bb23, (unsigned)(bb23 >> 32));
            mma_e4m3(za0, za1, za2, za3, A0, A1, A2, A3, bz, bz);
        }
    }
    {
        int r = lane >> 2, c2s = (lane & 3) * 2;
        float* sw = scratch + w*256;
        sw[r*16 + c2s]           = acc[0];
        sw[r*16 + c2s + 1]       = acc[1];
        sw[(r+8)*16 + c2s]       = acc[2];
        sw[(r+8)*16 + c2s + 1]   = acc[3];
        sw[r*16 + 8 + c2s]       = acc[4];
        sw[r*16 + 8 + c2s + 1]   = acc[5];
        sw[(r+8)*16 + 8 + c2s]   = acc[6];
        sw[(r+8)*16 + 8 + c2s+1] = acc[7];
        if ((lane & 3) == 0) {
            zs[w*16 + r]     = za0;
            zs[w*16 + 8 + r] = za2;
        }
    }
    __syncthreads();

    // ---- phase 5: cross-warp reduce, z-normalize, unscale, write bf16 [b][n][c] ----
    if (tid < 256) {
        int r = tid >> 4, c = tid & 15;
        float s = 0.f, zr = 0.f;
#pragma unroll
        for (int wi = 0; wi < 16; ++wi) {
            s  += scratch[wi*256 + r*16 + c];
            zr += zs[wi*16 + r];
        }
        float val = s / zr * g_vsinv[bc0 + c];
        g_aT[((size_t)b*NTOK + row0 + r)*CC + h*CHH + c] = __float2bfloat16(val);
    }
}

// =================================================================
// Kernel 3: out = x + wo @ attn via bf16 tensor cores.
// wo pre-converted (g_wo16), attn tile pre-converted [b][n][c] (g_aT).
// grid = (72, 2), 256 threads
// =================================================================
#define OC_STRIDE 136
#define OC_SMEM_BYTES ((128*OC_STRIDE + 32*OC_STRIDE) * 2)

__global__ __launch_bounds__(256) void outconv_kernel(
    const float* __restrict__ x, float* __restrict__ out)
{
    extern __shared__ __nv_bfloat16 smoc[];
    __nv_bfloat16* wos = smoc;                      // [128][136]
    __nv_bfloat16* ats = smoc + 128*OC_STRIDE;      // [32 tokens][136 channels]

    const int b  = blockIdx.y;
    const int n0 = blockIdx.x * 32;
    const int tid = threadIdx.x;

    {   // wo: 8192 u32 pairs
        const unsigned* wsrc = (const unsigned*)g_wo16;
        for (int l = tid; l < 8192; l += 256) {
            int row = l >> 6, cp = l & 63;
            *(unsigned*)&wos[row*OC_STRIDE + cp*2] = wsrc[l];
        }
    }
    {   // attn tile: 2048 u32 pairs
        const unsigned* asrc = (const unsigned*)(g_aT + (size_t)b*NTOK*CC) + (size_t)n0*64;
        for (int l = tid; l < 2048; l += 256) {
            int nl = l >> 6, cp = l & 63;
            *(unsigned*)&ats[nl*OC_STRIDE + cp*2] = asrc[l];
        }
    }
    __syncthreads();

    const int w = tid >> 5, lane = tid & 31;
    const int r = lane >> 2, kq = (lane & 3) * 2;

    float acc[4][4];
#pragma unroll
    for (int ng = 0; ng < 4; ++ng)
#pragma unroll
        for (int i = 0; i < 4; ++i) acc[ng][i] = 0.f;

#pragma unroll
    for (int kc = 0; kc < 8; ++kc) {
        const int k0 = kc * 16;
        unsigned a0 = *(const unsigned*)&wos[(w*16 + r)*OC_STRIDE + k0 + kq];
        unsigned a1 = *(const unsigned*)&wos[(w*16 + r + 8)*OC_STRIDE + k0 + kq];
        unsigned a2 = *(const unsigned*)&wos[(w*16 + r)*OC_STRIDE + k0 + kq + 8];
        unsigned a3 = *(const unsigned*)&wos[(w*16 + r + 8)*OC_STRIDE + k0 + kq + 8];
#pragma unroll
        for (int ng = 0; ng < 4; ++ng) {
            unsigned b0 = *(const unsigned*)&ats[(ng*8 + r)*OC_STRIDE + k0 + kq];
            unsigned b1 = *(const unsigned*)&ats[(ng*8 + r)*OC_STRIDE + k0 + kq + 8];
            mma_bf16(acc[ng][0], acc[ng][1], acc[ng][2], acc[ng][3],
                     a0, a1, a2, a3, b0, b1);
        }
    }

#pragma unroll
    for (int ng = 0; ng < 4; ++ng) {
        const int col = n0 + ng*8 + kq;
        size_t i0 = (size_t)(b*CC + w*16 + r)*NTOK + col;
        float2 x0 = *(const float2*)(x + i0);
        *(float2*)(out + i0) = make_float2(x0.x + acc[ng][0], x0.y + acc[ng][1]);
        size_t i1 = (size_t)(b*CC + w*16 + r + 8)*NTOK + col;
        float2 x1 = *(const float2*)(x + i1);
        *(float2*)(out + i1) = make_float2(x1.x + acc[ng][2], x1.y + acc[ng][3]);
    }
}

// =================================================================
extern "C" void kernel_launch(void* const* d_in, const int* in_sizes, int n_in,
                              void* d_out, int out_size)
{
    const float* x    = (const float*)d_in[0];
    const float* wq   = (const float*)d_in[1];
    const float* wk   = (const float*)d_in[2];
    const float* wv   = (const float*)d_in[3];
    const float* dwq  = (const float*)d_in[4];
    const float* dwk  = (const float*)d_in[5];
    const float* dwv  = (const float*)d_in[6];
    const float* wo   = (const float*)d_in[7];
    const float* temp = (const float*)d_in[8];
    float* out = (float*)d_out;

    cudaFuncSetAttribute(qkv_kernel, cudaFuncAttributeMaxDynamicSharedMemorySize, QKV_SMEM_BYTES);
    cudaFuncSetAttribute(attn_kernel, cudaFuncAttributeMaxDynamicSharedMemorySize, ATTN_SMEM_BYTES);
    cudaFuncSetAttribute(outconv_kernel, cudaFuncAttributeMaxDynamicSharedMemorySize, OC_SMEM_BYTES);

    qkv_kernel<<<BB*CC, 576, QKV_SMEM_BYTES>>>(x, wq, wk, wv, dwq, dwk, dwv, wo);
    attn_kernel<<<dim3(NTOK/16, BB*NHEADS), 512, ATTN_SMEM_BYTES>>>(temp);
    outconv_kernel<<<dim3(NTOK/32, BB), 256, OC_SMEM_BYTES>>>(x, out);
}